// round 11
// baseline (speedup 1.0000x reference)
#include <cuda_runtime.h>
#include <cuda_fp16.h>
#include <cstdint>
#include <cstddef>

#define BATCH 1024
#define INF   512
#define OUTF  100000
#define NTILE 782            // 782*128 = 100096 >= 100000

#define MARGIN_COS 0.8775825618903728f
#define MARGIN_SIN 0.4794255386042030f
#define LOGIT_SCALE 20.0f
#define W_PRESCALE 64.0f

static __device__ __half d_fhat[BATCH * INF];   // normalized features fp16

// ---------------------------------------------------------------------------
// helpers
// ---------------------------------------------------------------------------
#define LDSM4(fr, saddr) \
    asm volatile("ldmatrix.sync.aligned.m8n8.x4.shared.b16 {%0,%1,%2,%3},[%4];" \
                 : "=r"((fr)[0]), "=r"((fr)[1]), "=r"((fr)[2]), "=r"((fr)[3]) : "r"(saddr))

__device__ __forceinline__ void mma16816(float* c, const uint32_t* a, uint32_t b0, uint32_t b1) {
    asm volatile(
        "mma.sync.aligned.m16n8k16.row.col.f32.f16.f16.f32 "
        "{%0,%1,%2,%3},{%4,%5,%6,%7},{%8,%9},{%0,%1,%2,%3};"
        : "+f"(c[0]), "+f"(c[1]), "+f"(c[2]), "+f"(c[3])
        : "r"(a[0]), "r"(a[1]), "r"(a[2]), "r"(a[3]), "r"(b0), "r"(b1));
}

// A fragment (m16k16, row-major) loaded straight from global: canonical layout
//  a0,a1=(row, c0..c0+1)  a2,a3=(row+8, c0..c0+1)  a4,a5=(row, c0+8..9)  a6,a7=(row+8, ...)
#define LDGA(dst, po) do {                                                        \
    (dst)[0] = *reinterpret_cast<const uint32_t*>(pA + (po));                     \
    (dst)[1] = *reinterpret_cast<const uint32_t*>(pA + (po) + 8 * INF);           \
    (dst)[2] = *reinterpret_cast<const uint32_t*>(pA + (po) + 8);                 \
    (dst)[3] = *reinterpret_cast<const uint32_t*>(pA + (po) + 8 * INF + 8);       \
} while (0)

// ---------------------------------------------------------------------------
// Kernel 1: normalize features rows (exact fp32 norm), write fp16
// ---------------------------------------------------------------------------
__global__ void norm_features_k(const float* __restrict__ f) {
    int b = blockIdx.x;
    int t = threadIdx.x;  // 128 threads
    const float4* f4 = reinterpret_cast<const float4*>(f + (size_t)b * INF);
    float4 v = f4[t];
    float ss = v.x * v.x + v.y * v.y + v.z * v.z + v.w * v.w;
#pragma unroll
    for (int o = 16; o; o >>= 1) ss += __shfl_xor_sync(0xFFFFFFFFu, ss, o);
    __shared__ float red[4];
    if ((t & 31) == 0) red[t >> 5] = ss;
    __syncthreads();
    ss = red[0] + red[1] + red[2] + red[3];
    float inv = 1.0f / fmaxf(sqrtf(ss), 1e-12f);
    __half2* o2 = reinterpret_cast<__half2*>(d_fhat + (size_t)b * INF + t * 4);
    o2[0] = __floats2half2_rn(v.x * inv, v.y * inv);
    o2[1] = __floats2half2_rn(v.z * inv, v.w * inv);
}

// ---------------------------------------------------------------------------
// Fused kernel: one CTA (256 threads, 8 warps, 4M x 2N, 64x64 warp tiles)
//  per 128-class tile. W fp32 read once -> fp16 SMEM resident (133 KB).
//  A fragments loaded DIRECTLY from global (L2-resident, 1 MB total):
//  NO cp.async, NO smem staging, NO __syncthreads in the main loop.
// ---------------------------------------------------------------------------
#define LDSW 520                      // halves per W row (1040B: conflict-free ldsm)
#define SMEM_WINV 0
#define SMEM_W    1024
#define SMEM_TOTAL (1024 + 128 * LDSW * 2)         // 134144

__global__ void __launch_bounds__(256, 1)
arcface_fused_k(const float* __restrict__ w, const int* __restrict__ targets,
                float* __restrict__ out) {
    extern __shared__ char smem[];
    const uint32_t sb = (uint32_t)__cvta_generic_to_shared(smem);
    const int tid  = threadIdx.x;
    const int lane = tid & 31;
    const int wid  = tid >> 5;
    const int wm   = wid & 3;   // 4 warps in M (64 rows each)
    const int wn   = wid >> 2;  // 2 warps in N (64 cols each)
    const int nblk = blockIdx.x * 128;

    float* winv_s = reinterpret_cast<float*>(smem + SMEM_WINV);
    const uint32_t w_base = sb + SMEM_W;

    // ---- Phase 1: W fp32 -> fp16 SMEM (read once), per-class inverse norms ----
    {
        const int r = tid >> 1;        // class row in tile
        const int h = tid & 1;         // half-row (256 floats)
        const int cls = nblk + r;
        __half* wrow = reinterpret_cast<__half*>(smem + SMEM_W) + r * LDSW + h * 256;
        float ss = 0.0f;
        if (cls < OUTF) {
            const float4* src = reinterpret_cast<const float4*>(w + (size_t)cls * INF + h * 256);
#pragma unroll 8
            for (int j = 0; j < 64; ++j) {
                float4 v = src[j];
                ss += v.x * v.x + v.y * v.y + v.z * v.z + v.w * v.w;
                __half2* dst = reinterpret_cast<__half2*>(wrow + j * 4);
                dst[0] = __floats2half2_rn(v.x * W_PRESCALE, v.y * W_PRESCALE);
                dst[1] = __floats2half2_rn(v.z * W_PRESCALE, v.w * W_PRESCALE);
            }
        } else {
            __half2 z = __floats2half2_rn(0.f, 0.f);
#pragma unroll 8
            for (int j = 0; j < 64; ++j) {
                __half2* dst = reinterpret_cast<__half2*>(wrow + j * 4);
                dst[0] = z; dst[1] = z;
            }
        }
        float tot = ss + __shfl_xor_sync(0xFFFFFFFFu, ss, 1);
        if (h == 0)
            winv_s[r] = (cls < OUTF) ? 1.0f / (W_PRESCALE * fmaxf(sqrtf(tot), 1e-12f)) : 0.0f;
    }
    __syncthreads();   // the ONLY block-wide sync

    // ---- per-lane A pointer and per-warp B smem base ----
    const __half* __restrict__ pA =
        d_fhat + (size_t)(wm * 64 + (lane >> 2)) * INF + (lane & 3) * 2;
    const uint32_t lane_col = ((lane >> 4) << 4);           // 0 or 16 bytes
    const uint32_t b_off0 = (uint32_t)((wn * 64 + (lane & 7) + (((lane >> 3) & 1) << 3)) * (LDSW * 2))
                            + lane_col;

    uint32_t af[2][4][4];   // [buf][mi][reg]
    uint32_t bf[2][4][4];   // [buf][pi][reg]

    // preload fragments for step 0 (m=0, ks=0)
#pragma unroll
    for (int mi = 0; mi < 4; ++mi) LDGA(af[0][mi], mi * 16 * INF);
#pragma unroll
    for (int i = 0; i < 4; ++i)
        LDSM4(bf[0][i], w_base + b_off0 + (uint32_t)(i * 16 * LDSW * 2));

    float acc[4][8][4];

    for (int m = 0; m < 4; ++m) {
#pragma unroll
        for (int i = 0; i < 4; i++)
#pragma unroll
            for (int j = 0; j < 8; j++)
#pragma unroll
                for (int q = 0; q < 4; q++) acc[i][j][q] = 0.0f;

#pragma unroll 4
        for (int ks = 0; ks < 32; ++ks) {
            const int s = m * 32 + ks;
            const int c = s & 1, n = c ^ 1;

            // prefetch step s+1 fragments (no barrier: A from global, B resident)
            if (s + 1 < 128) {
                const int s1 = s + 1;
                const int po = ((s1 >> 5) * 256) * INF + (s1 & 31) * 16;
#pragma unroll
                for (int mi = 0; mi < 4; ++mi) LDGA(af[n][mi], po + mi * 16 * INF);
                const uint32_t bo = (uint32_t)((s1 & 31) * 32);
#pragma unroll
                for (int i = 0; i < 4; ++i)
                    LDSM4(bf[n][i], w_base + b_off0 + (uint32_t)(i * 16 * LDSW * 2) + bo);
            }

            // 32-mma burst
#pragma unroll
            for (int mi = 0; mi < 4; ++mi)
#pragma unroll
                for (int ni = 0; ni < 8; ++ni) {
                    const int pi = ni >> 1, sub = ni & 1;
                    mma16816(acc[mi][ni], af[c][mi], bf[c][pi][sub], bf[c][pi][sub + 2]);
                }
        }

        // ---- epilogue for this M-tile (register-only, no sync needed) ----
        const int rbase = m * 256 + wm * 64 + (lane >> 2);
#pragma unroll
        for (int ni = 0; ni < 8; ++ni) {
            const int cl = wn * 64 + ni * 8 + (lane & 3) * 2;  // local col
            const int c0 = nblk + cl;
            if (c0 >= OUTF) continue;
            const float2 wv = *reinterpret_cast<const float2*>(winv_s + cl);
#pragma unroll
            for (int mi = 0; mi < 4; ++mi) {
#pragma unroll
                for (int rr = 0; rr < 2; ++rr) {
                    const int row = rbase + mi * 16 + rr * 8;
                    float x0 = acc[mi][ni][rr * 2 + 0] * wv.x;
                    float x1 = acc[mi][ni][rr * 2 + 1] * wv.y;
                    x0 = fminf(fmaxf(x0, -1.0f), 1.0f);
                    x1 = fminf(fmaxf(x1, -1.0f), 1.0f);
                    const int t = targets[row];
                    if (t == c0)
                        x0 = x0 * MARGIN_COS - sqrtf(fmaxf(1.0f - x0 * x0, 0.0f)) * MARGIN_SIN;
                    if (t == c0 + 1)
                        x1 = x1 * MARGIN_COS - sqrtf(fmaxf(1.0f - x1 * x1, 0.0f)) * MARGIN_SIN;
                    float2 o = make_float2(x0 * LOGIT_SCALE, x1 * LOGIT_SCALE);
                    *reinterpret_cast<float2*>(out + (size_t)row * OUTF + c0) = o;
                }
            }
        }
    }
}

// ---------------------------------------------------------------------------
extern "C" void kernel_launch(void* const* d_in, const int* in_sizes, int n_in,
                              void* d_out, int out_size) {
    const float* feat = (const float*)d_in[0];
    const int*   tgt  = (const int*)d_in[1];   // int32 (JAX x64-disabled)
    const float* w    = (const float*)d_in[2];
    float* out = (float*)d_out;

    cudaFuncSetAttribute(arcface_fused_k, cudaFuncAttributeMaxDynamicSharedMemorySize, SMEM_TOTAL);
    norm_features_k<<<BATCH, 128>>>(feat);
    arcface_fused_k<<<NTILE, 256, SMEM_TOTAL>>>(w, tgt, out);
}

// round 12
// speedup vs baseline: 1.4132x; 1.4132x over previous
#include <cuda_runtime.h>
#include <cuda_fp16.h>
#include <cstdint>
#include <cstddef>

#define BATCH 1024
#define INF   512
#define OUTF  100000
#define NTILE 782            // 782*128 = 100096 >= 100000

#define MARGIN_COS 0.8775825618903728f
#define MARGIN_SIN 0.4794255386042030f
#define LOGIT_SCALE 20.0f
#define W_PRESCALE 64.0f

static __device__ __half d_fhat[BATCH * INF];   // normalized features fp16

// ---------------------------------------------------------------------------
// helpers
// ---------------------------------------------------------------------------
#define LDSM4(fr, saddr) \
    asm volatile("ldmatrix.sync.aligned.m8n8.x4.shared.b16 {%0,%1,%2,%3},[%4];" \
                 : "=r"((fr)[0]), "=r"((fr)[1]), "=r"((fr)[2]), "=r"((fr)[3]) : "r"(saddr))

__device__ __forceinline__ void mma16816(float* c, const uint32_t* a, uint32_t b0, uint32_t b1) {
    asm volatile(
        "mma.sync.aligned.m16n8k16.row.col.f32.f16.f16.f32 "
        "{%0,%1,%2,%3},{%4,%5,%6,%7},{%8,%9},{%0,%1,%2,%3};"
        : "+f"(c[0]), "+f"(c[1]), "+f"(c[2]), "+f"(c[3])
        : "r"(a[0]), "r"(a[1]), "r"(a[2]), "r"(a[3]), "r"(b0), "r"(b1));
}
__device__ __forceinline__ void cp_async16(uint32_t dst, const void* src) {
    asm volatile("cp.async.cg.shared.global [%0], [%1], 16;" :: "r"(dst), "l"(src));
}
#define CP_COMMIT() asm volatile("cp.async.commit_group;" ::: "memory")
#define CP_WAIT(N)  asm volatile("cp.async.wait_group %0;" :: "n"(N) : "memory")
#define GBAR(id)    asm volatile("bar.sync %0, 256;" :: "r"(id) : "memory")

// ---------------------------------------------------------------------------
// Kernel 1: normalize features rows (exact fp32 norm), write fp16
// ---------------------------------------------------------------------------
__global__ void norm_features_k(const float* __restrict__ f) {
    int b = blockIdx.x;
    int t = threadIdx.x;  // 128 threads
    const float4* f4 = reinterpret_cast<const float4*>(f + (size_t)b * INF);
    float4 v = f4[t];
    float ss = v.x * v.x + v.y * v.y + v.z * v.z + v.w * v.w;
#pragma unroll
    for (int o = 16; o; o >>= 1) ss += __shfl_xor_sync(0xFFFFFFFFu, ss, o);
    __shared__ float red[4];
    if ((t & 31) == 0) red[t >> 5] = ss;
    __syncthreads();
    ss = red[0] + red[1] + red[2] + red[3];
    float inv = 1.0f / fmaxf(sqrtf(ss), 1e-12f);
    __half2* o2 = reinterpret_cast<__half2*>(d_fhat + (size_t)b * INF + t * 4);
    o2[0] = __floats2half2_rn(v.x * inv, v.y * inv);
    o2[1] = __floats2half2_rn(v.z * inv, v.w * inv);
}

// ---------------------------------------------------------------------------
// Fused kernel: 512 threads = 2 INDEPENDENT groups of 8 warps.
//  Each group: 2Mx4N warps, 32x32 tiles, own 64-row M-slabs (interleaved),
//  own A double-buffers, own named barrier. W tile (128 classes) is shared
//  read-only SMEM. Groups phase-drift -> tensor pipe stays fed across one
//  group's barrier/ldsm phases.
// ---------------------------------------------------------------------------
#define LDSW 520                      // halves per W row (1040B: conflict-free ldsm)
#define LDSA 136                      // halves per A chunk row (272B: conflict-free)
#define SMEM_WINV 0
#define SMEM_W    1024
#define SMEM_A    (1024 + 128 * LDSW * 2)          // 134144
#define ABUF_SZ   (64 * LDSA * 2)                  // 17408 (64 rows x 128 halves)
#define SMEM_TOTAL (SMEM_A + 4 * ABUF_SZ)          // 203776

__global__ void __launch_bounds__(512, 1)
arcface_fused_k(const float* __restrict__ w, const int* __restrict__ targets,
                float* __restrict__ out) {
    extern __shared__ char smem[];
    const uint32_t sb = (uint32_t)__cvta_generic_to_shared(smem);
    const int tid  = threadIdx.x;
    const int lane = tid & 31;
    const int wid  = tid >> 5;
    const int g    = wid & 1;        // group id (interleaved across SMSPs)
    const int gwid = wid >> 1;       // warp id within group: 0..7
    const int gtid = gwid * 32 + lane;
    const int wm   = gwid & 1;       // 2 warps in M (32 rows each) -> 64-row slab
    const int wn   = gwid >> 1;      // 4 warps in N (32 cols each) -> 128 cols
    const int nblk = blockIdx.x * 128;

    float* winv_s = reinterpret_cast<float*>(smem + SMEM_WINV);
    const uint32_t w_base  = sb + SMEM_W;
    const uint32_t ag_base = sb + SMEM_A + (uint32_t)g * (2 * ABUF_SZ);

    // ---- prefetch this group's first A chunk (slab g, kc 0) ----
    {
#pragma unroll
        for (int k = 0; k < 4; ++k) {
            int i = gtid + k * 256;          // 0..1023
            int r = i >> 4, c16 = i & 15;
            const char* src = (const char*)(d_fhat + ((size_t)(g * 64 + r) << 9)) + c16 * 16;
            cp_async16(ag_base + r * (LDSA * 2) + c16 * 16, src);
        }
        CP_COMMIT();
    }

    // ---- Phase 1: W fp32 -> fp16 SMEM (read once), per-class inverse norms ----
    {
        const int r = tid >> 2;        // class row in tile
        const int h = tid & 3;         // quarter-row (128 floats)
        const int cls = nblk + r;
        __half* wrow = reinterpret_cast<__half*>(smem + SMEM_W) + r * LDSW + h * 128;
        float ss = 0.0f;
        if (cls < OUTF) {
            const float4* src = reinterpret_cast<const float4*>(w + (size_t)cls * INF + h * 128);
#pragma unroll 8
            for (int j = 0; j < 32; ++j) {
                float4 v = src[j];
                ss += v.x * v.x + v.y * v.y + v.z * v.z + v.w * v.w;
                __half2* dst = reinterpret_cast<__half2*>(wrow + j * 4);
                dst[0] = __floats2half2_rn(v.x * W_PRESCALE, v.y * W_PRESCALE);
                dst[1] = __floats2half2_rn(v.z * W_PRESCALE, v.w * W_PRESCALE);
            }
        } else {
            __half2 z = __floats2half2_rn(0.f, 0.f);
#pragma unroll 8
            for (int j = 0; j < 32; ++j) {
                __half2* dst = reinterpret_cast<__half2*>(wrow + j * 4);
                dst[0] = z; dst[1] = z;
            }
        }
        float tot = ss + __shfl_xor_sync(0xFFFFFFFFu, ss, 1);
        tot += __shfl_xor_sync(0xFFFFFFFFu, tot, 2);
        if (h == 0)
            winv_s[r] = (cls < OUTF) ? 1.0f / (W_PRESCALE * fmaxf(sqrtf(tot), 1e-12f)) : 0.0f;
    }
    CP_WAIT(0);
    __syncthreads();   // the ONLY block-wide sync (W + first A chunks visible)

    // ---- per-warp ldsm base addresses ----
    const uint32_t lane_col = ((lane >> 4) << 4);           // 0 or 16 bytes
    const uint32_t a_off0 = (uint32_t)((wm * 32 + (lane & 15)) * (LDSA * 2)) + lane_col;
    const uint32_t b_off0 = (uint32_t)((wn * 32 + (lane & 7) + (((lane >> 3) & 1) << 3)) * (LDSW * 2))
                            + lane_col;

    uint32_t af[2][2][4];   // [buf][mi][reg]
    uint32_t bf[2][2][4];   // [buf][pi][reg]

    // preload frags for chunk 0, ks 0
#pragma unroll
    for (int i = 0; i < 2; ++i) {
        LDSM4(af[0][i], ag_base + a_off0 + (uint32_t)(i * 16 * LDSA * 2));
        LDSM4(bf[0][i], w_base + b_off0 + (uint32_t)(i * 16 * LDSW * 2));
    }

    float acc[2][4][4];
    const int bar_id = g + 1;

    for (int j = 0; j < 8; ++j) {                // this group's M-slabs: g, g+2, ...
        const int slab = g + 2 * j;
#pragma unroll
        for (int a = 0; a < 2; a++)
#pragma unroll
            for (int b = 0; b < 4; b++)
#pragma unroll
                for (int qq = 0; qq < 4; qq++) acc[a][b][qq] = 0.0f;

#pragma unroll 1
        for (int kc = 0; kc < 4; ++kc) {         // K chunks of 128 halves
            const int q = j * 4 + kc;
            // prefetch next chunk (possibly next slab's kc0) into other buffer
            if (q + 1 < 32) {
                const int kcn = (q + 1) & 3;
                const int slabn = g + 2 * ((q + 1) >> 2);
                const uint32_t dbuf = ag_base + ((q + 1) & 1) * ABUF_SZ;
#pragma unroll
                for (int k = 0; k < 4; ++k) {
                    int i = gtid + k * 256;
                    int r = i >> 4, c16 = i & 15;
                    const char* src = (const char*)(d_fhat + ((size_t)(slabn * 64 + r) << 9))
                                      + kcn * 256 + c16 * 16;
                    cp_async16(dbuf + r * (LDSA * 2) + c16 * 16, src);
                }
                CP_COMMIT();
            }

            const uint32_t abuf = ag_base + (q & 1) * ABUF_SZ;
            const uint32_t boff = (uint32_t)(kc * 256);
#pragma unroll
            for (int ks = 0; ks < 8; ++ks) {
                const int c = ks & 1, n = c ^ 1;
                if (ks < 7) {
                    const uint32_t ko = (uint32_t)((ks + 1) * 32);
#pragma unroll
                    for (int i = 0; i < 2; ++i) {
                        LDSM4(af[n][i], abuf + a_off0 + (uint32_t)(i * 16 * LDSA * 2) + ko);
                        LDSM4(bf[n][i], w_base + b_off0 + (uint32_t)(i * 16 * LDSW * 2) + boff + ko);
                    }
                }
#pragma unroll
                for (int mi = 0; mi < 2; ++mi)
#pragma unroll
                    for (int ni = 0; ni < 4; ++ni) {
                        const int pi = ni >> 1, sub = ni & 1;
                        mma16816(acc[mi][ni], af[c][mi], bf[c][pi][sub], bf[c][pi][sub + 2]);
                    }
            }
            CP_WAIT(0);
            GBAR(bar_id);   // group-local barrier only

            // preload ks0 frags for the next chunk
            if (q + 1 < 32) {
                const uint32_t nabuf = ag_base + ((q + 1) & 1) * ABUF_SZ;
                const uint32_t nboff = (uint32_t)((((q + 1) & 3)) * 256);
#pragma unroll
                for (int i = 0; i < 2; ++i) {
                    LDSM4(af[0][i], nabuf + a_off0 + (uint32_t)(i * 16 * LDSA * 2));
                    LDSM4(bf[0][i], w_base + b_off0 + (uint32_t)(i * 16 * LDSW * 2) + nboff);
                }
            }
        }

        // ---- epilogue for this slab (register-only; overlaps other group) ----
        const int rbase = slab * 64 + wm * 32 + (lane >> 2);
#pragma unroll
        for (int ni = 0; ni < 4; ++ni) {
            const int cl = wn * 32 + ni * 8 + (lane & 3) * 2;  // local col
            const int c0 = nblk + cl;
            if (c0 >= OUTF) continue;
            const float2 wv = *reinterpret_cast<const float2*>(winv_s + cl);
#pragma unroll
            for (int mi = 0; mi < 2; ++mi) {
#pragma unroll
                for (int rr = 0; rr < 2; ++rr) {
                    const int row = rbase + mi * 16 + rr * 8;
                    float x0 = acc[mi][ni][rr * 2 + 0] * wv.x;
                    float x1 = acc[mi][ni][rr * 2 + 1] * wv.y;
                    x0 = fminf(fmaxf(x0, -1.0f), 1.0f);
                    x1 = fminf(fmaxf(x1, -1.0f), 1.0f);
                    const int t = targets[row];
                    if (t == c0)
                        x0 = x0 * MARGIN_COS - sqrtf(fmaxf(1.0f - x0 * x0, 0.0f)) * MARGIN_SIN;
                    if (t == c0 + 1)
                        x1 = x1 * MARGIN_COS - sqrtf(fmaxf(1.0f - x1 * x1, 0.0f)) * MARGIN_SIN;
                    float2 o = make_float2(x0 * LOGIT_SCALE, x1 * LOGIT_SCALE);
                    *reinterpret_cast<float2*>(out + (size_t)row * OUTF + c0) = o;
                }
            }
        }
    }
}

// ---------------------------------------------------------------------------
extern "C" void kernel_launch(void* const* d_in, const int* in_sizes, int n_in,
                              void* d_out, int out_size) {
    const float* feat = (const float*)d_in[0];
    const int*   tgt  = (const int*)d_in[1];   // int32 (JAX x64-disabled)
    const float* w    = (const float*)d_in[2];
    float* out = (float*)d_out;

    cudaFuncSetAttribute(arcface_fused_k, cudaFuncAttributeMaxDynamicSharedMemorySize, SMEM_TOTAL);
    norm_features_k<<<BATCH, 128>>>(feat);
    arcface_fused_k<<<NTILE, 512, SMEM_TOTAL>>>(w, tgt, out);
}